// round 5
// baseline (speedup 1.0000x reference)
#include <cuda_runtime.h>
#include <cuda_bf16.h>
#include <mma.h>
#include <cstdint>

using namespace nvcuda;

// ============================================================================
// RobustNeuralKalmanFilter: B=8, S=4096, H=512
//   noise = softplus(lstm @ W^T + b) : wmma bf16x3 GEMM (compiler-managed
//                                      fragments), self-checked, exact SIMT
//                                      f32x2 fallback
//   Kalman scan                      : segmented + contraction warm-up
// ============================================================================

static constexpr int B_ = 8;
static constexpr int S_ = 4096;
static constexpr int H_ = 512;
static constexpr int M_ = B_ * S_;   // 32768
static constexpr int N_ = 2 * H_;    // 1024
static constexpr int K_ = H_;        // 512

__device__ __align__(256) float g_noise[(size_t)M_ * N_];       // 128 MB
__device__ __align__(256) __nv_bfloat16 g_Ahi[(size_t)M_ * K_]; // 32 MB
__device__ __align__(256) __nv_bfloat16 g_Alo[(size_t)M_ * K_]; // 32 MB
__device__ __align__(256) __nv_bfloat16 g_Whi[(size_t)N_ * K_]; // 1 MB
__device__ __align__(256) __nv_bfloat16 g_Wlo[(size_t)N_ * K_]; // 1 MB
__device__ int g_flag;

__device__ __forceinline__ float softplus_f(float x) {
    return fmaxf(x, 0.0f) + log1pf(__expf(-fabsf(x)));
}

// ---------------------------------------------------------------------------
// fp32 -> bf16 hi/lo split
// ---------------------------------------------------------------------------
__global__ void split_kernel(const float* __restrict__ x,
                             __nv_bfloat16* __restrict__ hi,
                             __nv_bfloat16* __restrict__ lo, int n4)
{
    int i = blockIdx.x * blockDim.x + threadIdx.x;
    if (i >= n4) return;
    float4 v = *(const float4*)(x + (size_t)i * 4);
    float f[4] = {v.x, v.y, v.z, v.w};
    __nv_bfloat16 h[4], l[4];
#pragma unroll
    for (int j = 0; j < 4; j++) {
        h[j] = __float2bfloat16_rn(f[j]);
        l[j] = __float2bfloat16_rn(f[j] - __bfloat162float(h[j]));
    }
    *(__nv_bfloat162*)(hi + (size_t)i * 4)     = __nv_bfloat162(h[0], h[1]);
    *(__nv_bfloat162*)(hi + (size_t)i * 4 + 2) = __nv_bfloat162(h[2], h[3]);
    *(__nv_bfloat162*)(lo + (size_t)i * 4)     = __nv_bfloat162(l[0], l[1]);
    *(__nv_bfloat162*)(lo + (size_t)i * 4 + 2) = __nv_bfloat162(l[2], l[3]);
}

// ---------------------------------------------------------------------------
// wmma bf16x3 GEMM + bias + softplus.
// CTA 128x128, 8 warps in 2(M) x 4(N); each warp owns 64x32 = 4x2 wmma 16x16
// tiles. Fragments loaded DIRECTLY from global (ldm = K_/N_ strides) — no
// hand-written smem layout anywhere. acc = Ahi*Whi + Alo*Whi + Ahi*Wlo.
// ---------------------------------------------------------------------------
__global__ __launch_bounds__(256)
void gemm_wmma_kernel(const float* __restrict__ bias)
{
    __shared__ __align__(16) float scratch[8][16 * 17];   // per-warp epilogue

    const int tid = threadIdx.x;
    const int wid = tid >> 5;
    const int lid = tid & 31;
    const int m0 = blockIdx.y * 128;
    const int n0 = blockIdx.x * 128;
    const int wm = wid >> 2;          // 0..1 -> +64 rows
    const int wn = wid & 3;           // 0..3 -> +32 cols

    const int mrow = m0 + wm * 64;    // warp's first A row
    const int ncol = n0 + wn * 32;    // warp's first W row / C col

    wmma::fragment<wmma::accumulator, 16, 16, 16, float> acc[4][2];
#pragma unroll
    for (int mi = 0; mi < 4; mi++)
#pragma unroll
        for (int nj = 0; nj < 2; nj++)
            wmma::fill_fragment(acc[mi][nj], 0.0f);

    for (int k = 0; k < K_; k += 16) {
        wmma::fragment<wmma::matrix_a, 16, 16, 16, __nv_bfloat16, wmma::row_major> ah[4], al[4];
        wmma::fragment<wmma::matrix_b, 16, 16, 16, __nv_bfloat16, wmma::col_major> bh[2], bl[2];
#pragma unroll
        for (int mi = 0; mi < 4; mi++) {
            const size_t off = (size_t)(mrow + mi * 16) * K_ + k;
            wmma::load_matrix_sync(ah[mi], g_Ahi + off, K_);
            wmma::load_matrix_sync(al[mi], g_Alo + off, K_);
        }
#pragma unroll
        for (int nj = 0; nj < 2; nj++) {
            // B(k, n) = W[n][k]  ->  col_major with ldm = K_
            const size_t off = (size_t)(ncol + nj * 16) * K_ + k;
            wmma::load_matrix_sync(bh[nj], g_Whi + off, K_);
            wmma::load_matrix_sync(bl[nj], g_Wlo + off, K_);
        }
#pragma unroll
        for (int mi = 0; mi < 4; mi++)
#pragma unroll
            for (int nj = 0; nj < 2; nj++) {
                wmma::mma_sync(acc[mi][nj], ah[mi], bh[nj], acc[mi][nj]);
                wmma::mma_sync(acc[mi][nj], al[mi], bh[nj], acc[mi][nj]);
                wmma::mma_sync(acc[mi][nj], ah[mi], bl[nj], acc[mi][nj]);
            }
    }

    // ---- epilogue: per-fragment via per-warp smem scratch ----
    const int r  = lid >> 1;           // 0..15
    const int cb = (lid & 1) * 8;      // 0 or 8
#pragma unroll
    for (int mi = 0; mi < 4; mi++)
#pragma unroll
        for (int nj = 0; nj < 2; nj++) {
            wmma::store_matrix_sync(scratch[wid], acc[mi][nj], 17, wmma::mem_row_major);
            __syncwarp();
            const int col = ncol + nj * 16 + cb;
            const int row = mrow + mi * 16 + r;
            float o[8];
#pragma unroll
            for (int j = 0; j < 8; j++)
                o[j] = softplus_f(scratch[wid][r * 17 + cb + j] + bias[col + j]);
            float* p = g_noise + (size_t)row * N_ + col;
            *(float4*)p       = make_float4(o[0], o[1], o[2], o[3]);
            *(float4*)(p + 4) = make_float4(o[4], o[5], o[6], o[7]);
            __syncwarp();
        }
}

// ---------------------------------------------------------------------------
// Verification: recompute 2048 scattered elements in fp32 SIMT.
// ---------------------------------------------------------------------------
__global__ void reset_flag_kernel() { if (threadIdx.x == 0) g_flag = 0; }

__global__ void check_kernel(const float* __restrict__ A,
                             const float* __restrict__ W,
                             const float* __restrict__ bias)
{
    const int i = blockIdx.x * blockDim.x + threadIdx.x;   // 0..2047
    const int m = (i * 12289 + 7) & (M_ - 1);
    const int n = (i * 577 + 3) & (N_ - 1);
    const float* a = A + (size_t)m * K_;
    const float* w = W + (size_t)n * K_;
    float s = 0.0f;
#pragma unroll 8
    for (int k = 0; k < K_; k++) s = fmaf(a[k], w[k], s);
    const float ref = softplus_f(s + bias[n]);
    const float got = g_noise[(size_t)m * N_ + n];
    if (fabsf(got - ref) > 5e-3f * (fabsf(ref) + 0.1f))
        atomicOr(&g_flag, 1);
}

// ---------------------------------------------------------------------------
// Fallback: exact SIMT f32x2 GEMM (proven R1 kernel + flag early-out).
// ---------------------------------------------------------------------------
__global__ __launch_bounds__(256, 2)
void gemm_fixup_kernel(const float* __restrict__ A,
                       const float* __restrict__ W,
                       const float* __restrict__ bias)
{
    if (*(volatile int*)&g_flag == 0) return;

    __shared__ __align__(16) float As[2][16][132];
    __shared__ __align__(16) float Ws[2][16][132];

    const int t  = threadIdx.x;
    const int n0 = blockIdx.x * 128;
    const int m0 = blockIdx.y * 128;
    const int lr = t >> 2;
    const int lq = t & 3;

    const float* Ap = A + (size_t)(m0 + lr) * K_ + lq * 4;
    const float* Wp = W + (size_t)(n0 + lr) * K_ + lq * 4;

    {
        float4 a0 = *(const float4*)Ap;
        float4 a1 = *(const float4*)(Ap + (size_t)64 * K_);
        float4 w0 = *(const float4*)Wp;
        float4 w1 = *(const float4*)(Wp + (size_t)64 * K_);
        float va0[4] = {a0.x, a0.y, a0.z, a0.w};
        float va1[4] = {a1.x, a1.y, a1.z, a1.w};
        float vw0[4] = {w0.x, w0.y, w0.z, w0.w};
        float vw1[4] = {w1.x, w1.y, w1.z, w1.w};
#pragma unroll
        for (int c = 0; c < 4; c++) {
            As[0][lq * 4 + c][lr]      = va0[c];
            As[0][lq * 4 + c][lr + 64] = va1[c];
            Ws[0][lq * 4 + c][lr]      = vw0[c];
            Ws[0][lq * 4 + c][lr + 64] = vw1[c];
        }
    }
    __syncthreads();

    unsigned long long acc[8][4];
#pragma unroll
    for (int i = 0; i < 8; i++)
#pragma unroll
        for (int j = 0; j < 4; j++) acc[i][j] = 0ull;

    const int ty = t >> 4;
    const int tx = t & 15;

    for (int kk = 0; kk < 32; ++kk) {
        float4 na0, na1, nw0, nw1;
        if (kk < 31) {
            const float* ap = Ap + (kk + 1) * 16;
            const float* wp = Wp + (kk + 1) * 16;
            na0 = *(const float4*)ap;
            na1 = *(const float4*)(ap + (size_t)64 * K_);
            nw0 = *(const float4*)wp;
            nw1 = *(const float4*)(wp + (size_t)64 * K_);
        }
        const int cb = kk & 1;
#pragma unroll
        for (int k = 0; k < 16; k++) {
            float4 av0 = *(const float4*)&As[cb][k][ty * 8];
            float4 av1 = *(const float4*)&As[cb][k][ty * 8 + 4];
            ulonglong2 bv0 = *(const ulonglong2*)&Ws[cb][k][tx * 8];
            ulonglong2 bv1 = *(const ulonglong2*)&Ws[cb][k][tx * 8 + 4];
            float av[8] = {av0.x, av0.y, av0.z, av0.w,
                           av1.x, av1.y, av1.z, av1.w};
#pragma unroll
            for (int i = 0; i < 8; i++) {
                unsigned long long a2;
                asm("mov.b64 %0, {%1, %1};" : "=l"(a2) : "f"(av[i]));
                asm("fma.rn.f32x2 %0, %1, %2, %0;" : "+l"(acc[i][0]) : "l"(a2), "l"(bv0.x));
                asm("fma.rn.f32x2 %0, %1, %2, %0;" : "+l"(acc[i][1]) : "l"(a2), "l"(bv0.y));
                asm("fma.rn.f32x2 %0, %1, %2, %0;" : "+l"(acc[i][2]) : "l"(a2), "l"(bv1.x));
                asm("fma.rn.f32x2 %0, %1, %2, %0;" : "+l"(acc[i][3]) : "l"(a2), "l"(bv1.y));
            }
        }
        if (kk < 31) {
            const int nb = cb ^ 1;
            float va0[4] = {na0.x, na0.y, na0.z, na0.w};
            float va1[4] = {na1.x, na1.y, na1.z, na1.w};
            float vw0[4] = {nw0.x, nw0.y, nw0.z, nw0.w};
            float vw1[4] = {nw1.x, nw1.y, nw1.z, nw1.w};
#pragma unroll
            for (int c = 0; c < 4; c++) {
                As[nb][lq * 4 + c][lr]      = va0[c];
                As[nb][lq * 4 + c][lr + 64] = va1[c];
                Ws[nb][lq * 4 + c][lr]      = vw0[c];
                Ws[nb][lq * 4 + c][lr + 64] = vw1[c];
            }
        }
        __syncthreads();
    }

    const int nb = n0 + tx * 8;
    float bb[8];
#pragma unroll
    for (int j = 0; j < 8; j++) bb[j] = bias[nb + j];

#pragma unroll
    for (int i = 0; i < 8; i++) {
        const int m = m0 + ty * 8 + i;
        float o[8];
#pragma unroll
        for (int jp = 0; jp < 4; jp++) {
            unsigned long long v = acc[i][jp];
            float lo = __uint_as_float((unsigned)(v & 0xffffffffull));
            float hi = __uint_as_float((unsigned)(v >> 32));
            o[2 * jp]     = softplus_f(lo + bb[2 * jp]);
            o[2 * jp + 1] = softplus_f(hi + bb[2 * jp + 1]);
        }
        float* np_ = g_noise + (size_t)m * N_ + nb;
        *(float4*)np_       = make_float4(o[0], o[1], o[2], o[3]);
        *(float4*)(np_ + 4) = make_float4(o[4], o[5], o[6], o[7]);
    }
}

// ---------------------------------------------------------------------------
// Segmented Kalman scan with 256-step contraction warm-up. 32768 threads.
// ---------------------------------------------------------------------------
static constexpr int SEG  = 512;
static constexpr int LOOK = 256;

__device__ __forceinline__ void load_chunk_scan(const float* __restrict__ zp,
                                                const float* __restrict__ np,
                                                int base,
                                                float (&Z)[16], float (&Q)[16], float (&R)[16])
{
#pragma unroll
    for (int i = 0; i < 16; i++) {
        const size_t s = (size_t)(base + i);
        Z[i] = zp[s * H_];
        Q[i] = np[s * N_];
        R[i] = np[s * N_ + H_] + 1e-6f;
    }
}

__global__ void kalman_scan_kernel(const float* __restrict__ z,
                                   float* __restrict__ out)
{
    const int t   = blockIdx.x * blockDim.x + threadIdx.x;
    const int h   = t & (H_ - 1);
    const int b   = (t >> 9) & 7;
    const int seg = t >> 12;

    const int start = seg * SEG;
    const int ws    = (seg == 0) ? 0 : start - LOOK;
    const int nch   = (start - ws + SEG) >> 4;
    const int skip  = (start - ws) >> 4;

    const float* zp = z       + (size_t)b * S_ * H_ + (size_t)ws * H_ + h;
    const float* np = g_noise + (size_t)b * S_ * N_ + (size_t)ws * N_ + h;
    float*       op = out     + (size_t)b * S_ * H_ + (size_t)ws * H_ + h;

    float ZA[16], QA[16], RA[16], ZB[16], QB[16], RB[16];

    load_chunk_scan(zp, np, 0, ZA, QA, RA);
    float state = ZA[0];
    float P = 0.1f;

    for (int c = 0; c < nch; c += 2) {
        load_chunk_scan(zp, np, (c + 1) * 16, ZB, QB, RB);
        const bool wrA = (c >= skip);
#pragma unroll
        for (int i = 0; i < 16; i++) {
            const float Pp = P + QA[i];
            const float K  = __fdividef(Pp, Pp + RA[i]);
            state = fmaf(K, ZA[i] - state, state);
            P = K * RA[i];
            if (wrA) op[(size_t)(c * 16 + i) * H_] = state;
        }
        if (c + 2 < nch) load_chunk_scan(zp, np, (c + 2) * 16, ZA, QA, RA);
        const bool wrB = (c + 1 >= skip);
#pragma unroll
        for (int i = 0; i < 16; i++) {
            const float Pp = P + QB[i];
            const float K  = __fdividef(Pp, Pp + RB[i]);
            state = fmaf(K, ZB[i] - state, state);
            P = K * RB[i];
            if (wrB) op[(size_t)((c + 1) * 16 + i) * H_] = state;
        }
    }
}

// ---------------------------------------------------------------------------
extern "C" void kernel_launch(void* const* d_in, const int* in_sizes, int n_in,
                              void* d_out, int out_size)
{
    const float* lstm = (const float*)d_in[0];
    const float* W    = (const float*)d_in[1];
    const float* bias = (const float*)d_in[2];
    float*       out  = (float*)d_out;

    split_kernel<<<(M_ * K_ / 4 + 255) / 256, 256>>>(lstm, g_Ahi, g_Alo, M_ * K_ / 4);
    split_kernel<<<(N_ * K_ / 4 + 255) / 256, 256>>>(W,    g_Whi, g_Wlo, N_ * K_ / 4);

    // wmma GEMM (grid.x = 8 N-tiles fastest -> A L2 reuse across co-running CTAs)
    gemm_wmma_kernel<<<dim3(8, 256), 256>>>(bias);

    // Deterministic self-check + exact fallback (no-op when wmma is correct)
    reset_flag_kernel<<<1, 32>>>();
    check_kernel<<<8, 256>>>(lstm, W, bias);
    gemm_fixup_kernel<<<dim3(8, 256), 256>>>(lstm, W, bias);

    // Segmented scan
    kalman_scan_kernel<<<128, 256>>>(lstm, out);
}

// round 6
// speedup vs baseline: 3.5800x; 3.5800x over previous
#include <cuda_runtime.h>
#include <cuda_bf16.h>
#include <cstdint>

// ============================================================================
// RobustNeuralKalmanFilter: B=8, S=4096, H=512
//   noise = softplus(lstm @ W^T + b) : mma.sync bf16x3 GEMM, self-checked,
//                                      exact SIMT f32x2 fallback
//   Kalman scan                      : segmented + contraction warm-up
//
// KEY FIX vs R4/R5: __device__ symbols are NEVER passed as kernel args from
// host (that passes the host shadow address; on GB300/ATS the GPU silently
// writes host memory). All scratch symbols are referenced from device code.
// ============================================================================

static constexpr int B_ = 8;
static constexpr int S_ = 4096;
static constexpr int H_ = 512;
static constexpr int M_ = B_ * S_;   // 32768
static constexpr int N_ = 2 * H_;    // 1024
static constexpr int K_ = H_;        // 512

__device__ __align__(256) float g_noise[(size_t)M_ * N_];       // 128 MB
__device__ __align__(256) __nv_bfloat16 g_Ahi[(size_t)M_ * K_]; // 32 MB
__device__ __align__(256) __nv_bfloat16 g_Alo[(size_t)M_ * K_]; // 32 MB
__device__ __align__(256) __nv_bfloat16 g_Whi[(size_t)N_ * K_]; // 1 MB
__device__ __align__(256) __nv_bfloat16 g_Wlo[(size_t)N_ * K_]; // 1 MB
__device__ int g_flag;

// ---------------------------------------------------------------------------
__device__ __forceinline__ uint32_t smem_u32(const void* p) {
    uint32_t a;
    asm("{ .reg .u64 t; cvta.to.shared.u64 t, %1; cvt.u32.u64 %0, t; }" : "=r"(a) : "l"(p));
    return a;
}
__device__ __forceinline__ void cp_async16(uint32_t dst, const void* src) {
    asm volatile("cp.async.cg.shared.global [%0], [%1], 16;" :: "r"(dst), "l"(src));
}
#define CP_COMMIT() asm volatile("cp.async.commit_group;" ::: "memory")
#define CP_WAIT1()  asm volatile("cp.async.wait_group 1;" ::: "memory")

__device__ __forceinline__ void ldsm_x4(uint32_t* r, uint32_t addr) {
    asm volatile("ldmatrix.sync.aligned.m8n8.x4.shared.b16 {%0,%1,%2,%3}, [%4];"
                 : "=r"(r[0]), "=r"(r[1]), "=r"(r[2]), "=r"(r[3]) : "r"(addr));
}
__device__ __forceinline__ void mma16816(float* c, const uint32_t* a, const uint32_t* b) {
    asm volatile("mma.sync.aligned.m16n8k16.row.col.f32.bf16.bf16.f32 "
                 "{%0,%1,%2,%3}, {%4,%5,%6,%7}, {%8,%9}, {%0,%1,%2,%3};"
                 : "+f"(c[0]), "+f"(c[1]), "+f"(c[2]), "+f"(c[3])
                 : "r"(a[0]), "r"(a[1]), "r"(a[2]), "r"(a[3]), "r"(b[0]), "r"(b[1]));
}
__device__ __forceinline__ float softplus_f(float x) {
    return fmaxf(x, 0.0f) + log1pf(__expf(-fabsf(x)));
}

// ---------------------------------------------------------------------------
// fp32 -> bf16 hi/lo split. mode 0: A (lstm) -> g_Ahi/g_Alo
//                           mode 1: W        -> g_Whi/g_Wlo
// Device symbols referenced directly in device code (THE fix).
// ---------------------------------------------------------------------------
__global__ void split_kernel(const float* __restrict__ x, int n4, int mode)
{
    int i = blockIdx.x * blockDim.x + threadIdx.x;
    if (i >= n4) return;
    __nv_bfloat16* hi = mode ? g_Whi : g_Ahi;
    __nv_bfloat16* lo = mode ? g_Wlo : g_Alo;
    float4 v = *(const float4*)(x + (size_t)i * 4);
    float f[4] = {v.x, v.y, v.z, v.w};
    __nv_bfloat16 h[4], l[4];
#pragma unroll
    for (int j = 0; j < 4; j++) {
        h[j] = __float2bfloat16_rn(f[j]);
        l[j] = __float2bfloat16_rn(f[j] - __bfloat162float(h[j]));
    }
    *(__nv_bfloat162*)(hi + (size_t)i * 4)     = __nv_bfloat162(h[0], h[1]);
    *(__nv_bfloat162*)(hi + (size_t)i * 4 + 2) = __nv_bfloat162(h[2], h[3]);
    *(__nv_bfloat162*)(lo + (size_t)i * 4)     = __nv_bfloat162(l[0], l[1]);
    *(__nv_bfloat162*)(lo + (size_t)i * 4 + 2) = __nv_bfloat162(l[2], l[3]);
}

// ---------------------------------------------------------------------------
// mma.sync bf16x3 GEMM + bias + softplus.
// CTA 128x128, K-chunk 32, 8 warps (2Mx4N, each 64x32), cp.async dbl-buffer.
// smem pitch 80B: ldmatrix row phase (r*5+s)%8 bijective -> conflict-free.
// ---------------------------------------------------------------------------
static constexpr int PITCH = 80;
static constexpr int TILE_B = 128 * PITCH;
static constexpr int STAGE_B = 4 * TILE_B;
static constexpr int GEMM_SMEM = 2 * STAGE_B;   // 81920

__global__ __launch_bounds__(256, 2)
void gemm_mma_kernel(const float* __restrict__ bias)
{
    extern __shared__ __align__(128) char smem[];
    const uint32_t sb = smem_u32(smem);
    const int tid = threadIdx.x;
    const int wid = tid >> 5;
    const int lid = tid & 31;
    const int m0 = blockIdx.y * 128;
    const int n0 = blockIdx.x * 128;

    auto load_chunk = [&](int c, int s) {
        const int kb = c * 32;
        const uint32_t st = sb + s * STAGE_B;
#pragma unroll
        for (int i = 0; i < 2; i++) {
            int u = tid + i * 256;
            int row = u >> 2, seg = u & 3;
            uint32_t d = (uint32_t)(row * PITCH + seg * 16);
            size_t ga = (size_t)(m0 + row) * K_ + kb + seg * 8;
            size_t gw = (size_t)(n0 + row) * K_ + kb + seg * 8;
            cp_async16(st + d,              g_Ahi + ga);
            cp_async16(st + TILE_B + d,     g_Alo + ga);
            cp_async16(st + 2 * TILE_B + d, g_Whi + gw);
            cp_async16(st + 3 * TILE_B + d, g_Wlo + gw);
        }
    };

    load_chunk(0, 0); CP_COMMIT();
    load_chunk(1, 1); CP_COMMIT();

    float acc[4][4][4];
#pragma unroll
    for (int i = 0; i < 4; i++)
#pragma unroll
        for (int j = 0; j < 4; j++)
#pragma unroll
            for (int q = 0; q < 4; q++) acc[i][j][q] = 0.0f;

    const int wm = wid >> 2;
    const int wn = wid & 3;
    const uint32_t lrow = (uint32_t)(lid & 15) * PITCH + (uint32_t)(lid >> 4) * 16;

    for (int c = 0; c < 16; ++c) {
        const int s = c & 1;
        CP_WAIT1();
        __syncthreads();

        const uint32_t st = sb + s * STAGE_B;
        const uint32_t aBase = st + (uint32_t)(wm * 64) * PITCH + lrow;
        const uint32_t bBase = st + 2 * TILE_B + (uint32_t)(wn * 32) * PITCH + lrow;

#pragma unroll
        for (int kk = 0; kk < 2; kk++) {
            uint32_t ah[16], al[16], bh[8], bl[8];
#pragma unroll
            for (int mi = 0; mi < 4; mi++) {
                ldsm_x4(ah + mi * 4, aBase + (uint32_t)(mi * 16 * PITCH) + kk * 32);
                ldsm_x4(al + mi * 4, aBase + TILE_B + (uint32_t)(mi * 16 * PITCH) + kk * 32);
            }
#pragma unroll
            for (int nb = 0; nb < 2; nb++) {
                ldsm_x4(bh + nb * 4, bBase + (uint32_t)(nb * 16 * PITCH) + kk * 32);
                ldsm_x4(bl + nb * 4, bBase + TILE_B + (uint32_t)(nb * 16 * PITCH) + kk * 32);
            }
#pragma unroll
            for (int mi = 0; mi < 4; mi++)
#pragma unroll
                for (int nj = 0; nj < 4; nj++) {
                    const int nb = nj >> 1, od = nj & 1;
                    uint32_t bfh[2] = {bh[nb * 4 + od], bh[nb * 4 + 2 + od]};
                    uint32_t bfl[2] = {bl[nb * 4 + od], bl[nb * 4 + 2 + od]};
                    mma16816(acc[mi][nj], ah + mi * 4, bfh);
                    mma16816(acc[mi][nj], al + mi * 4, bfh);
                    mma16816(acc[mi][nj], ah + mi * 4, bfl);
                }
        }
        __syncthreads();
        if (c + 2 < 16) load_chunk(c + 2, s);
        CP_COMMIT();
    }

    const int q  = lid >> 2;
    const int tq = lid & 3;
    const int colb = n0 + wn * 32;
#pragma unroll
    for (int nj = 0; nj < 4; nj++) {
        const int col = colb + nj * 8 + tq * 2;
        const float2 bv = *(const float2*)&bias[col];
#pragma unroll
        for (int mi = 0; mi < 4; mi++) {
            const int r0 = m0 + wm * 64 + mi * 16 + q;
            float2 v0, v1;
            v0.x = softplus_f(acc[mi][nj][0] + bv.x);
            v0.y = softplus_f(acc[mi][nj][1] + bv.y);
            v1.x = softplus_f(acc[mi][nj][2] + bv.x);
            v1.y = softplus_f(acc[mi][nj][3] + bv.y);
            *(float2*)&g_noise[(size_t)r0 * N_ + col]       = v0;
            *(float2*)&g_noise[(size_t)(r0 + 8) * N_ + col] = v1;
        }
    }
}

// ---------------------------------------------------------------------------
// Verification: recompute 2048 scattered elements in fp32 SIMT.
// bf16x3 true error ~3e-6; tolerance 5e-3*(|ref|+0.1) -> only structural
// bugs can fire the flag.
// ---------------------------------------------------------------------------
__global__ void reset_flag_kernel() { if (threadIdx.x == 0) g_flag = 0; }

__global__ void check_kernel(const float* __restrict__ A,
                             const float* __restrict__ W,
                             const float* __restrict__ bias)
{
    const int i = blockIdx.x * blockDim.x + threadIdx.x;   // 0..2047
    const int m = (i * 12289 + 7) & (M_ - 1);
    const int n = (i * 577 + 3) & (N_ - 1);
    const float* a = A + (size_t)m * K_;
    const float* w = W + (size_t)n * K_;
    float s = 0.0f;
#pragma unroll 8
    for (int k = 0; k < K_; k++) s = fmaf(a[k], w[k], s);
    const float ref = softplus_f(s + bias[n]);
    const float got = g_noise[(size_t)m * N_ + n];
    if (fabsf(got - ref) > 5e-3f * (fabsf(ref) + 0.1f))
        atomicOr(&g_flag, 1);
}

// ---------------------------------------------------------------------------
// Fallback: exact SIMT f32x2 GEMM (proven R1 kernel + flag early-out).
// ---------------------------------------------------------------------------
__global__ __launch_bounds__(256, 2)
void gemm_fixup_kernel(const float* __restrict__ A,
                       const float* __restrict__ W,
                       const float* __restrict__ bias)
{
    if (*(volatile int*)&g_flag == 0) return;

    __shared__ __align__(16) float As[2][16][132];
    __shared__ __align__(16) float Ws[2][16][132];

    const int t  = threadIdx.x;
    const int n0 = blockIdx.x * 128;
    const int m0 = blockIdx.y * 128;
    const int lr = t >> 2;
    const int lq = t & 3;

    const float* Ap = A + (size_t)(m0 + lr) * K_ + lq * 4;
    const float* Wp = W + (size_t)(n0 + lr) * K_ + lq * 4;

    {
        float4 a0 = *(const float4*)Ap;
        float4 a1 = *(const float4*)(Ap + (size_t)64 * K_);
        float4 w0 = *(const float4*)Wp;
        float4 w1 = *(const float4*)(Wp + (size_t)64 * K_);
        float va0[4] = {a0.x, a0.y, a0.z, a0.w};
        float va1[4] = {a1.x, a1.y, a1.z, a1.w};
        float vw0[4] = {w0.x, w0.y, w0.z, w0.w};
        float vw1[4] = {w1.x, w1.y, w1.z, w1.w};
#pragma unroll
        for (int c = 0; c < 4; c++) {
            As[0][lq * 4 + c][lr]      = va0[c];
            As[0][lq * 4 + c][lr + 64] = va1[c];
            Ws[0][lq * 4 + c][lr]      = vw0[c];
            Ws[0][lq * 4 + c][lr + 64] = vw1[c];
        }
    }
    __syncthreads();

    unsigned long long acc[8][4];
#pragma unroll
    for (int i = 0; i < 8; i++)
#pragma unroll
        for (int j = 0; j < 4; j++) acc[i][j] = 0ull;

    const int ty = t >> 4;
    const int tx = t & 15;

    for (int kk = 0; kk < 32; ++kk) {
        float4 na0, na1, nw0, nw1;
        if (kk < 31) {
            const float* ap = Ap + (kk + 1) * 16;
            const float* wp = Wp + (kk + 1) * 16;
            na0 = *(const float4*)ap;
            na1 = *(const float4*)(ap + (size_t)64 * K_);
            nw0 = *(const float4*)wp;
            nw1 = *(const float4*)(wp + (size_t)64 * K_);
        }
        const int cb = kk & 1;
#pragma unroll
        for (int k = 0; k < 16; k++) {
            float4 av0 = *(const float4*)&As[cb][k][ty * 8];
            float4 av1 = *(const float4*)&As[cb][k][ty * 8 + 4];
            ulonglong2 bv0 = *(const ulonglong2*)&Ws[cb][k][tx * 8];
            ulonglong2 bv1 = *(const ulonglong2*)&Ws[cb][k][tx * 8 + 4];
            float av[8] = {av0.x, av0.y, av0.z, av0.w,
                           av1.x, av1.y, av1.z, av1.w};
#pragma unroll
            for (int i = 0; i < 8; i++) {
                unsigned long long a2;
                asm("mov.b64 %0, {%1, %1};" : "=l"(a2) : "f"(av[i]));
                asm("fma.rn.f32x2 %0, %1, %2, %0;" : "+l"(acc[i][0]) : "l"(a2), "l"(bv0.x));
                asm("fma.rn.f32x2 %0, %1, %2, %0;" : "+l"(acc[i][1]) : "l"(a2), "l"(bv0.y));
                asm("fma.rn.f32x2 %0, %1, %2, %0;" : "+l"(acc[i][2]) : "l"(a2), "l"(bv1.x));
                asm("fma.rn.f32x2 %0, %1, %2, %0;" : "+l"(acc[i][3]) : "l"(a2), "l"(bv1.y));
            }
        }
        if (kk < 31) {
            const int nb = cb ^ 1;
            float va0[4] = {na0.x, na0.y, na0.z, na0.w};
            float va1[4] = {na1.x, na1.y, na1.z, na1.w};
            float vw0[4] = {nw0.x, nw0.y, nw0.z, nw0.w};
            float vw1[4] = {nw1.x, nw1.y, nw1.z, nw1.w};
#pragma unroll
            for (int c = 0; c < 4; c++) {
                As[nb][lq * 4 + c][lr]      = va0[c];
                As[nb][lq * 4 + c][lr + 64] = va1[c];
                Ws[nb][lq * 4 + c][lr]      = vw0[c];
                Ws[nb][lq * 4 + c][lr + 64] = vw1[c];
            }
        }
        __syncthreads();
    }

    const int nb = n0 + tx * 8;
    float bb[8];
#pragma unroll
    for (int j = 0; j < 8; j++) bb[j] = bias[nb + j];

#pragma unroll
    for (int i = 0; i < 8; i++) {
        const int m = m0 + ty * 8 + i;
        float o[8];
#pragma unroll
        for (int jp = 0; jp < 4; jp++) {
            unsigned long long v = acc[i][jp];
            float lo = __uint_as_float((unsigned)(v & 0xffffffffull));
            float hi = __uint_as_float((unsigned)(v >> 32));
            o[2 * jp]     = softplus_f(lo + bb[2 * jp]);
            o[2 * jp + 1] = softplus_f(hi + bb[2 * jp + 1]);
        }
        float* np_ = g_noise + (size_t)m * N_ + nb;
        *(float4*)np_       = make_float4(o[0], o[1], o[2], o[3]);
        *(float4*)(np_ + 4) = make_float4(o[4], o[5], o[6], o[7]);
    }
}

// ---------------------------------------------------------------------------
// Segmented Kalman scan with 256-step contraction warm-up. 32768 threads.
// ---------------------------------------------------------------------------
static constexpr int SEG  = 512;
static constexpr int LOOK = 256;

__device__ __forceinline__ void load_chunk_scan(const float* __restrict__ zp,
                                                const float* __restrict__ np,
                                                int base,
                                                float (&Z)[16], float (&Q)[16], float (&R)[16])
{
#pragma unroll
    for (int i = 0; i < 16; i++) {
        const size_t s = (size_t)(base + i);
        Z[i] = zp[s * H_];
        Q[i] = np[s * N_];
        R[i] = np[s * N_ + H_] + 1e-6f;
    }
}

__global__ void kalman_scan_kernel(const float* __restrict__ z,
                                   float* __restrict__ out)
{
    const int t   = blockIdx.x * blockDim.x + threadIdx.x;
    const int h   = t & (H_ - 1);
    const int b   = (t >> 9) & 7;
    const int seg = t >> 12;

    const int start = seg * SEG;
    const int ws    = (seg == 0) ? 0 : start - LOOK;
    const int nch   = (start - ws + SEG) >> 4;
    const int skip  = (start - ws) >> 4;

    const float* zp = z       + (size_t)b * S_ * H_ + (size_t)ws * H_ + h;
    const float* np = g_noise + (size_t)b * S_ * N_ + (size_t)ws * N_ + h;
    float*       op = out     + (size_t)b * S_ * H_ + (size_t)ws * H_ + h;

    float ZA[16], QA[16], RA[16], ZB[16], QB[16], RB[16];

    load_chunk_scan(zp, np, 0, ZA, QA, RA);
    float state = ZA[0];
    float P = 0.1f;

    for (int c = 0; c < nch; c += 2) {
        load_chunk_scan(zp, np, (c + 1) * 16, ZB, QB, RB);
        const bool wrA = (c >= skip);
#pragma unroll
        for (int i = 0; i < 16; i++) {
            const float Pp = P + QA[i];
            const float K  = __fdividef(Pp, Pp + RA[i]);
            state = fmaf(K, ZA[i] - state, state);
            P = K * RA[i];
            if (wrA) op[(size_t)(c * 16 + i) * H_] = state;
        }
        if (c + 2 < nch) load_chunk_scan(zp, np, (c + 2) * 16, ZA, QA, RA);
        const bool wrB = (c + 1 >= skip);
#pragma unroll
        for (int i = 0; i < 16; i++) {
            const float Pp = P + QB[i];
            const float K  = __fdividef(Pp, Pp + RB[i]);
            state = fmaf(K, ZB[i] - state, state);
            P = K * RB[i];
            if (wrB) op[(size_t)((c + 1) * 16 + i) * H_] = state;
        }
    }
}

// ---------------------------------------------------------------------------
extern "C" void kernel_launch(void* const* d_in, const int* in_sizes, int n_in,
                              void* d_out, int out_size)
{
    const float* lstm = (const float*)d_in[0];
    const float* W    = (const float*)d_in[1];
    const float* bias = (const float*)d_in[2];
    float*       out  = (float*)d_out;

    cudaFuncSetAttribute(gemm_mma_kernel,
                         cudaFuncAttributeMaxDynamicSharedMemorySize, GEMM_SMEM);

    // bf16 hi/lo splits -> device symbols written from DEVICE code
    split_kernel<<<(M_ * K_ / 4 + 255) / 256, 256>>>(lstm, M_ * K_ / 4, 0);
    split_kernel<<<(N_ * K_ / 4 + 255) / 256, 256>>>(W,    N_ * K_ / 4, 1);

    // Fast tensor-core GEMM
    gemm_mma_kernel<<<dim3(8, 256), 256, GEMM_SMEM>>>(bias);

    // Deterministic self-check + exact fallback (no-op when mma is correct)
    reset_flag_kernel<<<1, 32>>>();
    check_kernel<<<8, 256>>>(lstm, W, bias);
    gemm_fixup_kernel<<<dim3(8, 256), 256>>>(lstm, W, bias);

    // Segmented scan
    kalman_scan_kernel<<<128, 256>>>(lstm, out);
}